// round 10
// baseline (speedup 1.0000x reference)
#include <cuda_runtime.h>
#include <math_constants.h>

// Problem constants (fixed shapes from setup_inputs)
#define BB 8
#define LP1 25
#define LL 24
#define TT 512
#define DD 1024
#define PP 128
#define TOPK 3

#define SPLIT1 16   // T-splits for score pass  -> 8*24*16 = 3072 blocks
#define SPLIT3 64   // T-splits for gather pass -> 8*64    = 512 blocks
#define FBLK   4    // p-slices per batch in k_final -> 32 blocks

// Output layout: flattened tuple in reference order, all fp32
#define OFF_PROJ   0
#define OFF_SCORES 1024
#define OFF_IDX    1216
#define OFF_SEL    1240

// Scratch (device globals; allocation-free)
__device__ float g_score_partial[BB * LL * SPLIT1];
__device__ int   g_topk_idx[BB * TOPK];
__device__ float g_topk_val[BB * TOPK];
__device__ float g_pooled[BB * DD];      // atomic-max accumulator (32 KB)
__device__ int   g_cnt;                  // last-block counter (self-resetting)

// Exact, order-independent float atomic max (bit trick).
__device__ __forceinline__ void atomicMaxFloat(float* addr, float v) {
    if (v >= 0.0f) {
        atomicMax((int*)addr, __float_as_int(v));
    } else {
        atomicMin((unsigned int*)addr, __float_as_uint(v));
    }
}

// ---------------------------------------------------------------------------
// Kernel 1: per-(b,l,s) score partials over 32 t-rows each; first 32 blocks
// also init g_pooled. The LAST block additionally does softmax + top-3.
// ---------------------------------------------------------------------------
__global__ __launch_bounds__(256) void k_scores(const float* __restrict__ x,
                                                const float* __restrict__ w_score,
                                                const float* __restrict__ b_score,
                                                float* __restrict__ out) {
    const int blk = blockIdx.x;           // 0 .. BB*LL*SPLIT1-1
    const int tid = threadIdx.x;

    // init atomic-max accumulator for the gather pass
    if (blk < 32) g_pooled[blk * 256 + tid] = -CUDART_INF_F;

    const int s   = blk % SPLIT1;
    const int bl  = blk / SPLIT1;
    const int l   = bl % LL;
    const int b   = bl / LL;

    const float4* __restrict__ base =
        (const float4*)(x + ((size_t)b * LP1 + (size_t)(l + 1)) * TT * DD);
    const float4 w4 = ((const float4*)w_score)[tid];

    float acc = 0.f;
    const int t0 = s * (TT / SPLIT1);     // 32 rows per block
    #pragma unroll 8
    for (int t = t0; t < t0 + TT / SPLIT1; ++t) {
        float4 v = base[(size_t)t * (DD / 4) + tid];
        acc += v.x * w4.x + v.y * w4.y + v.z * w4.z + v.w * w4.w;
    }

    __shared__ float sm[256];
    sm[tid] = acc;
    __syncthreads();
    #pragma unroll
    for (int st = 128; st > 0; st >>= 1) {
        if (tid < st) sm[tid] += sm[tid + st];
        __syncthreads();
    }

    // publish partial, then last-block detection
    __shared__ int s_last;
    if (tid == 0) {
        g_score_partial[bl * SPLIT1 + s] = sm[0];
        __threadfence();
        int old = atomicAdd(&g_cnt, 1);
        s_last = (old == BB * LL * SPLIT1 - 1);
    }
    __syncthreads();
    if (!s_last) return;

    // ---- fused top-k (runs in exactly one block, after all partials) ----
    __threadfence();
    __shared__ float sc[BB * LL];
    if (tid < BB * LL) {
        float v = 0.f;
        #pragma unroll
        for (int i = 0; i < SPLIT1; ++i) v += g_score_partial[tid * SPLIT1 + i];
        v = v * (1.0f / (float)TT) + b_score[0];
        sc[tid] = v;
        out[OFF_SCORES + tid] = v;
    }
    __syncthreads();

    if (tid < BB) {
        const int bb = tid;
        float m = -CUDART_INF_F;
        #pragma unroll
        for (int l2 = 0; l2 < LL; ++l2) m = fmaxf(m, sc[bb * LL + l2]);
        float p[LL];
        float sum = 0.f;
        #pragma unroll
        for (int l2 = 0; l2 < LL; ++l2) { p[l2] = expf(sc[bb * LL + l2] - m); sum += p[l2]; }
        const float inv = 1.0f / sum;
        #pragma unroll
        for (int l2 = 0; l2 < LL; ++l2) p[l2] *= inv;

        bool used[LL];
        #pragma unroll
        for (int l2 = 0; l2 < LL; ++l2) used[l2] = false;

        for (int k = 0; k < TOPK; ++k) {
            int   best = 0;
            float bv   = -CUDART_INF_F;
            #pragma unroll
            for (int l2 = 0; l2 < LL; ++l2) {
                if (!used[l2] && p[l2] > bv) { bv = p[l2]; best = l2; }
            }
            used[best] = true;
            g_topk_idx[bb * TOPK + k] = best;
            g_topk_val[bb * TOPK + k] = bv;
            out[OFF_IDX + bb * TOPK + k] = (float)best;
        }
    }
    // reset counter for the next graph replay (deterministic)
    if (tid == 0) g_cnt = 0;
}

// ---------------------------------------------------------------------------
// Kernel 3: gather 3 selected layers -> write selected_layers output
// (streaming stores), fused weighted sum + block-local max over T, then
// exact atomic max into g_pooled. Interleaved loop, 8 t-rows per block.
// ---------------------------------------------------------------------------
__global__ __launch_bounds__(256) void k_gather(const float* __restrict__ x,
                                                float* __restrict__ out) {
    const int blk = blockIdx.x;             // 0 .. BB*SPLIT3-1
    const int s   = blk % SPLIT3;
    const int b   = blk / SPLIT3;
    const int tid = threadIdx.x;

    const int i0 = g_topk_idx[b * TOPK + 0];
    const int i1 = g_topk_idx[b * TOPK + 1];
    const int i2 = g_topk_idx[b * TOPK + 2];
    const float v0 = g_topk_val[b * TOPK + 0];
    const float v1 = g_topk_val[b * TOPK + 1];
    const float v2 = g_topk_val[b * TOPK + 2];

    const float4* __restrict__ p0 =
        (const float4*)(x + ((size_t)b * LP1 + (size_t)(i0 + 1)) * TT * DD);
    const float4* __restrict__ p1 =
        (const float4*)(x + ((size_t)b * LP1 + (size_t)(i1 + 1)) * TT * DD);
    const float4* __restrict__ p2 =
        (const float4*)(x + ((size_t)b * LP1 + (size_t)(i2 + 1)) * TT * DD);

    float* __restrict__ sel = out + OFF_SEL;
    float4* __restrict__ o0 = (float4*)(sel + ((size_t)b * TOPK + 0) * TT * DD);
    float4* __restrict__ o1 = (float4*)(sel + ((size_t)b * TOPK + 1) * TT * DD);
    float4* __restrict__ o2 = (float4*)(sel + ((size_t)b * TOPK + 2) * TT * DD);

    const int TPS = TT / SPLIT3;   // 8 rows per block
    float4 mx = make_float4(-CUDART_INF_F, -CUDART_INF_F, -CUDART_INF_F, -CUDART_INF_F);

    #pragma unroll
    for (int tt = 0; tt < TPS; ++tt) {
        const size_t off = (size_t)(s * TPS + tt) * (DD / 4) + tid;
        float4 a = p0[off];
        float4 c = p1[off];
        float4 e = p2[off];
        __stcs(&o0[off], a);
        __stcs(&o1[off], c);
        __stcs(&o2[off], e);
        float4 w;
        w.x = v0 * a.x + v1 * c.x + v2 * e.x;
        w.y = v0 * a.y + v1 * c.y + v2 * e.y;
        w.z = v0 * a.z + v1 * c.z + v2 * e.z;
        w.w = v0 * a.w + v1 * c.w + v2 * e.w;
        mx.x = fmaxf(mx.x, w.x);
        mx.y = fmaxf(mx.y, w.y);
        mx.z = fmaxf(mx.z, w.z);
        mx.w = fmaxf(mx.w, w.w);
    }

    float* gp = g_pooled + (size_t)b * DD + tid * 4;
    atomicMaxFloat(gp + 0, mx.x);
    atomicMaxFloat(gp + 1, mx.y);
    atomicMaxFloat(gp + 2, mx.z);
    atomicMaxFloat(gp + 3, mx.w);
}

// ---------------------------------------------------------------------------
// Kernel 4 (v3): grid = BB*FBLK = 32 blocks, block = 256 threads (NO 64-reg
// cap -> wv[32] truly stays in registers). Block (b, pb) computes outputs
// p in [32*pb, 32*pb+32). Warp w covers d in [128w, 128w+128): 4 rounds of
// {32 hoisted coalesced loads -> 32 FMAs} => MLP 32, ~4 round-trips total.
// ---------------------------------------------------------------------------
__global__ __launch_bounds__(256) void k_final(const float* __restrict__ gamma,
                                               const float* __restrict__ beta,
                                               const float* __restrict__ w_proj,
                                               const float* __restrict__ b_proj,
                                               float* __restrict__ out) {
    const int b    = blockIdx.x >> 2;     // FBLK = 4
    const int pb   = blockIdx.x & 3;
    const int tid  = threadIdx.x;
    const int lane = tid & 31, warp = tid >> 5;

    __shared__ float normed[DD];
    __shared__ float red[8], red2[8];
    __shared__ float s_stats[2];
    __shared__ float part[256];

    // --- LN: load pooled as float4 (4 per thread), reduce ---
    const float4 v = ((const float4*)(g_pooled + (size_t)b * DD))[tid];
    {
        float s1 = v.x + v.y + v.z + v.w;
        float s2 = v.x * v.x + v.y * v.y + v.z * v.z + v.w * v.w;
        #pragma unroll
        for (int o = 16; o > 0; o >>= 1) {
            s1 += __shfl_down_sync(0xffffffffu, s1, o);
            s2 += __shfl_down_sync(0xffffffffu, s2, o);
        }
        if (lane == 0) { red[warp] = s1; red2[warp] = s2; }
    }
    __syncthreads();
    if (tid == 0) {
        float s1 = 0.f, s2 = 0.f;
        #pragma unroll
        for (int i = 0; i < 8; ++i) { s1 += red[i]; s2 += red2[i]; }
        float mu  = s1 * (1.0f / (float)DD);
        float var = s2 * (1.0f / (float)DD) - mu * mu;
        s_stats[0] = mu;
        s_stats[1] = rsqrtf(var + 1e-5f);
    }
    __syncthreads();
    {
        const float mu = s_stats[0], rstd = s_stats[1];
        const float4 g4  = ((const float4*)gamma)[tid];
        const float4 be4 = ((const float4*)beta)[tid];
        float4 n;
        n.x = (v.x - mu) * rstd * g4.x + be4.x;
        n.y = (v.y - mu) * rstd * g4.y + be4.y;
        n.z = (v.z - mu) * rstd * g4.z + be4.z;
        n.w = (v.w - mu) * rstd * g4.w + be4.w;
        ((float4*)normed)[tid] = n;
    }
    __syncthreads();

    // --- GEMV slice: p = 32*pb + lane; warp w covers d in [128w, 128w+128) ---
    {
        const int p  = pb * 32 + lane;
        const int d0 = warp * 128;
        const float* __restrict__ wp = w_proj + (size_t)d0 * PP + p;
        float a0 = 0.f, a1 = 0.f, a2 = 0.f, a3 = 0.f;
        #pragma unroll
        for (int r = 0; r < 4; ++r) {
            // hoisted batch: 32 independent coalesced loads
            float wv[32];
            #pragma unroll
            for (int i = 0; i < 32; ++i)
                wv[i] = wp[(size_t)(r * 32 + i) * PP];
            const int db = d0 + r * 32;
            #pragma unroll
            for (int i = 0; i < 32; i += 4) {
                a0 = fmaf(normed[db + i + 0], wv[i + 0], a0);
                a1 = fmaf(normed[db + i + 1], wv[i + 1], a1);
                a2 = fmaf(normed[db + i + 2], wv[i + 2], a2);
                a3 = fmaf(normed[db + i + 3], wv[i + 3], a3);
            }
        }
        part[tid] = (a0 + a1) + (a2 + a3);
    }
    __syncthreads();
    if (tid < 32) {
        const int p = pb * 32 + tid;
        float acc = b_proj[p];
        #pragma unroll
        for (int c = 0; c < 8; ++c) acc += part[c * 32 + tid];
        out[OFF_PROJ + b * PP + p] = acc;
    }
}

// ---------------------------------------------------------------------------
// Launch
// ---------------------------------------------------------------------------
extern "C" void kernel_launch(void* const* d_in, const int* in_sizes, int n_in,
                              void* d_out, int out_size) {
    const float* x       = (const float*)d_in[0];  // wav2vec_ft (8,25,512,1024)
    const float* w_score = (const float*)d_in[1];  // (1024,1)
    const float* b_score = (const float*)d_in[2];  // (1,)
    const float* ln_g    = (const float*)d_in[3];  // (1024,)
    const float* ln_b    = (const float*)d_in[4];  // (1024,)
    const float* w_proj  = (const float*)d_in[5];  // (1024,128)
    const float* b_proj  = (const float*)d_in[6];  // (128,)
    float* out = (float*)d_out;

    k_scores<<<BB * LL * SPLIT1, 256>>>(x, w_score, b_score, out);
    k_gather<<<BB * SPLIT3, 256>>>(x, out);
    k_final<<<BB * FBLK, 256>>>(ln_g, ln_b, w_proj, b_proj, out);
}

// round 11
// speedup vs baseline: 1.0352x; 1.0352x over previous
#include <cuda_runtime.h>
#include <math_constants.h>

// Problem constants (fixed shapes from setup_inputs)
#define BB 8
#define LP1 25
#define LL 24
#define TT 512
#define DD 1024
#define PP 128
#define TOPK 3

#define SPLIT1 16   // T-splits for score pass  -> 8*24*16 = 3072 blocks
#define SPLIT3 64   // T-splits for gather pass -> 8*64    = 512 blocks
#define FBLK   4    // p-slices per batch in k_final -> 32 blocks

// Output layout: flattened tuple in reference order, all fp32
#define OFF_PROJ   0
#define OFF_SCORES 1024
#define OFF_IDX    1216
#define OFF_SEL    1240

// Scratch (device globals; allocation-free)
__device__ float        g_score_partial[BB * LL * SPLIT1];
__device__ int          g_topk_idx[BB * TOPK];
__device__ float        g_topk_val[BB * TOPK];
__device__ unsigned int g_pooled_key[BB * DD];   // monotone-key atomic-max accum
__device__ int          g_cnt;                   // last-block counter (self-resetting)

// Monotone float <-> uint key: uint order == float order (exact max).
__device__ __forceinline__ unsigned int fkey(float v) {
    unsigned int u = __float_as_uint(v);
    return (u & 0x80000000u) ? ~u : (u | 0x80000000u);
}
__device__ __forceinline__ float finv(unsigned int k) {
    return __uint_as_float((k & 0x80000000u) ? (k ^ 0x80000000u) : ~k);
}

// ---------------------------------------------------------------------------
// Kernel 1: per-(b,l,s) score partials over 32 t-rows each; first 32 blocks
// also init g_pooled_key. The LAST block additionally does softmax + top-3.
// ---------------------------------------------------------------------------
__global__ __launch_bounds__(256) void k_scores(const float* __restrict__ x,
                                                const float* __restrict__ w_score,
                                                const float* __restrict__ b_score,
                                                float* __restrict__ out) {
    const int blk = blockIdx.x;           // 0 .. BB*LL*SPLIT1-1
    const int tid = threadIdx.x;

    // init atomic-max key accumulator (0 is the minimal key)
    if (blk < 32) g_pooled_key[blk * 256 + tid] = 0u;

    const int s   = blk % SPLIT1;
    const int bl  = blk / SPLIT1;
    const int l   = bl % LL;
    const int b   = bl / LL;

    const float4* __restrict__ base =
        (const float4*)(x + ((size_t)b * LP1 + (size_t)(l + 1)) * TT * DD);
    const float4 w4 = ((const float4*)w_score)[tid];

    float acc = 0.f;
    const int t0 = s * (TT / SPLIT1);     // 32 rows per block
    #pragma unroll 8
    for (int t = t0; t < t0 + TT / SPLIT1; ++t) {
        float4 v = base[(size_t)t * (DD / 4) + tid];
        acc += v.x * w4.x + v.y * w4.y + v.z * w4.z + v.w * w4.w;
    }

    __shared__ float sm[256];
    sm[tid] = acc;
    __syncthreads();
    #pragma unroll
    for (int st = 128; st > 0; st >>= 1) {
        if (tid < st) sm[tid] += sm[tid + st];
        __syncthreads();
    }

    // publish partial, then last-block detection
    __shared__ int s_last;
    if (tid == 0) {
        g_score_partial[bl * SPLIT1 + s] = sm[0];
        __threadfence();
        int old = atomicAdd(&g_cnt, 1);
        s_last = (old == BB * LL * SPLIT1 - 1);
    }
    __syncthreads();
    if (!s_last) return;

    // ---- fused top-k (runs in exactly one block, after all partials) ----
    __threadfence();
    __shared__ float sc[BB * LL];
    if (tid < BB * LL) {
        float v = 0.f;
        #pragma unroll
        for (int i = 0; i < SPLIT1; ++i) v += g_score_partial[tid * SPLIT1 + i];
        v = v * (1.0f / (float)TT) + b_score[0];
        sc[tid] = v;
        out[OFF_SCORES + tid] = v;
    }
    __syncthreads();

    if (tid < BB) {
        const int bb = tid;
        float m = -CUDART_INF_F;
        #pragma unroll
        for (int l2 = 0; l2 < LL; ++l2) m = fmaxf(m, sc[bb * LL + l2]);
        float p[LL];
        float sum = 0.f;
        #pragma unroll
        for (int l2 = 0; l2 < LL; ++l2) { p[l2] = expf(sc[bb * LL + l2] - m); sum += p[l2]; }
        const float inv = 1.0f / sum;
        #pragma unroll
        for (int l2 = 0; l2 < LL; ++l2) p[l2] *= inv;

        bool used[LL];
        #pragma unroll
        for (int l2 = 0; l2 < LL; ++l2) used[l2] = false;

        for (int k = 0; k < TOPK; ++k) {
            int   best = 0;
            float bv   = -CUDART_INF_F;
            #pragma unroll
            for (int l2 = 0; l2 < LL; ++l2) {
                if (!used[l2] && p[l2] > bv) { bv = p[l2]; best = l2; }
            }
            used[best] = true;
            g_topk_idx[bb * TOPK + k] = best;
            g_topk_val[bb * TOPK + k] = bv;
            out[OFF_IDX + bb * TOPK + k] = (float)best;
        }
    }
    // reset counter for the next graph replay (deterministic)
    if (tid == 0) g_cnt = 0;
}

// ---------------------------------------------------------------------------
// Kernel 3: gather 3 selected layers -> write selected_layers output
// (streaming stores), fused weighted sum + block-local max over T, then
// branchless key-atomic max into g_pooled_key.
// B DESCENDING block order: wave 1 reads the batches the score pass touched
// last (still L2-resident).
// ---------------------------------------------------------------------------
__global__ __launch_bounds__(256) void k_gather(const float* __restrict__ x,
                                                float* __restrict__ out) {
    const int blk = blockIdx.x;             // 0 .. BB*SPLIT3-1
    const int s   = blk % SPLIT3;
    const int b   = (BB - 1) - blk / SPLIT3;   // descending: hot batches first
    const int tid = threadIdx.x;

    const int i0 = g_topk_idx[b * TOPK + 0];
    const int i1 = g_topk_idx[b * TOPK + 1];
    const int i2 = g_topk_idx[b * TOPK + 2];
    const float v0 = g_topk_val[b * TOPK + 0];
    const float v1 = g_topk_val[b * TOPK + 1];
    const float v2 = g_topk_val[b * TOPK + 2];

    const float4* __restrict__ p0 =
        (const float4*)(x + ((size_t)b * LP1 + (size_t)(i0 + 1)) * TT * DD);
    const float4* __restrict__ p1 =
        (const float4*)(x + ((size_t)b * LP1 + (size_t)(i1 + 1)) * TT * DD);
    const float4* __restrict__ p2 =
        (const float4*)(x + ((size_t)b * LP1 + (size_t)(i2 + 1)) * TT * DD);

    float* __restrict__ sel = out + OFF_SEL;
    float4* __restrict__ o0 = (float4*)(sel + ((size_t)b * TOPK + 0) * TT * DD);
    float4* __restrict__ o1 = (float4*)(sel + ((size_t)b * TOPK + 1) * TT * DD);
    float4* __restrict__ o2 = (float4*)(sel + ((size_t)b * TOPK + 2) * TT * DD);

    const int TPS = TT / SPLIT3;   // 8 rows per block
    float4 mx = make_float4(-CUDART_INF_F, -CUDART_INF_F, -CUDART_INF_F, -CUDART_INF_F);

    #pragma unroll
    for (int tt = 0; tt < TPS; ++tt) {
        const size_t off = (size_t)(s * TPS + tt) * (DD / 4) + tid;
        float4 a = p0[off];
        float4 c = p1[off];
        float4 e = p2[off];
        __stcs(&o0[off], a);
        __stcs(&o1[off], c);
        __stcs(&o2[off], e);
        float4 w;
        w.x = v0 * a.x + v1 * c.x + v2 * e.x;
        w.y = v0 * a.y + v1 * c.y + v2 * e.y;
        w.z = v0 * a.z + v1 * c.z + v2 * e.z;
        w.w = v0 * a.w + v1 * c.w + v2 * e.w;
        mx.x = fmaxf(mx.x, w.x);
        mx.y = fmaxf(mx.y, w.y);
        mx.z = fmaxf(mx.z, w.z);
        mx.w = fmaxf(mx.w, w.w);
    }

    unsigned int* gp = g_pooled_key + (size_t)b * DD + tid * 4;
    atomicMax(gp + 0, fkey(mx.x));
    atomicMax(gp + 1, fkey(mx.y));
    atomicMax(gp + 2, fkey(mx.z));
    atomicMax(gp + 3, fkey(mx.w));
}

// ---------------------------------------------------------------------------
// Kernel 4 (R8 version, measured best): grid = BB*FBLK, block = 1024.
// w_proj prefetch hoisted ahead of LN; GEMV on the prefetched values.
// ---------------------------------------------------------------------------
__global__ __launch_bounds__(1024) void k_final(const float* __restrict__ gamma,
                                                const float* __restrict__ beta,
                                                const float* __restrict__ w_proj,
                                                const float* __restrict__ b_proj,
                                                float* __restrict__ out) {
    const int b    = blockIdx.x >> 2;     // FBLK = 4
    const int pb   = blockIdx.x & 3;
    const int tid  = threadIdx.x;
    const int lane = tid & 31, warp = tid >> 5;

    __shared__ float normed[DD];
    __shared__ float red[32], red2[32];
    __shared__ float s_stats[2];
    __shared__ float part[1024];

    // start the w_proj fetch IMMEDIATELY (independent of LN)
    const int p  = pb * 32 + lane;
    const int d0 = warp * 32;
    const float* __restrict__ wp = w_proj + (size_t)d0 * PP + p;
    float wv[32];
    #pragma unroll
    for (int i = 0; i < 32; ++i)
        wv[i] = wp[(size_t)i * PP];

    const float m = finv(g_pooled_key[(size_t)b * DD + tid]);

    // LN stats
    {
        float s1 = m, s2 = m * m;
        #pragma unroll
        for (int o = 16; o > 0; o >>= 1) {
            s1 += __shfl_down_sync(0xffffffffu, s1, o);
            s2 += __shfl_down_sync(0xffffffffu, s2, o);
        }
        if (lane == 0) { red[warp] = s1; red2[warp] = s2; }
    }
    __syncthreads();
    if (tid < 32) {
        float s1 = red[tid], s2 = red2[tid];
        #pragma unroll
        for (int o = 16; o > 0; o >>= 1) {
            s1 += __shfl_down_sync(0xffffffffu, s1, o);
            s2 += __shfl_down_sync(0xffffffffu, s2, o);
        }
        if (tid == 0) {
            float mu  = s1 * (1.0f / (float)DD);
            float var = s2 * (1.0f / (float)DD) - mu * mu;
            s_stats[0] = mu;
            s_stats[1] = rsqrtf(var + 1e-5f);
        }
    }
    __syncthreads();

    normed[tid] = (m - s_stats[0]) * s_stats[1] * gamma[tid] + beta[tid];
    __syncthreads();

    // GEMV slice: FMAs on the pre-fetched values, 4 accumulators.
    {
        float a0 = 0.f, a1 = 0.f, a2 = 0.f, a3 = 0.f;
        #pragma unroll
        for (int i = 0; i < 32; i += 4) {
            a0 = fmaf(normed[d0 + i + 0], wv[i + 0], a0);
            a1 = fmaf(normed[d0 + i + 1], wv[i + 1], a1);
            a2 = fmaf(normed[d0 + i + 2], wv[i + 2], a2);
            a3 = fmaf(normed[d0 + i + 3], wv[i + 3], a3);
        }
        part[tid] = (a0 + a1) + (a2 + a3);
    }
    __syncthreads();
    if (tid < 32) {
        const int pp = pb * 32 + tid;
        float acc = b_proj[pp];
        #pragma unroll
        for (int c = 0; c < 32; ++c) acc += part[c * 32 + tid];
        out[OFF_PROJ + b * PP + pp] = acc;
    }
}

// ---------------------------------------------------------------------------
// Launch
// ---------------------------------------------------------------------------
extern "C" void kernel_launch(void* const* d_in, const int* in_sizes, int n_in,
                              void* d_out, int out_size) {
    const float* x       = (const float*)d_in[0];  // wav2vec_ft (8,25,512,1024)
    const float* w_score = (const float*)d_in[1];  // (1024,1)
    const float* b_score = (const float*)d_in[2];  // (1,)
    const float* ln_g    = (const float*)d_in[3];  // (1024,)
    const float* ln_b    = (const float*)d_in[4];  // (1024,)
    const float* w_proj  = (const float*)d_in[5];  // (1024,128)
    const float* b_proj  = (const float*)d_in[6];  // (128,)
    float* out = (float*)d_out;

    k_scores<<<BB * LL * SPLIT1, 256>>>(x, w_score, b_score, out);
    k_gather<<<BB * SPLIT3, 256>>>(x, out);
    k_final<<<BB * FBLK, 1024>>>(ln_g, ln_b, w_proj, b_proj, out);
}

// round 12
// speedup vs baseline: 1.0384x; 1.0031x over previous
#include <cuda_runtime.h>
#include <math_constants.h>

// Problem constants (fixed shapes from setup_inputs)
#define BB 8
#define LP1 25
#define LL 24
#define TT 512
#define DD 1024
#define PP 128
#define TOPK 3

#define SPLIT1 16   // T-splits for score pass  -> 8*24*16 = 3072 blocks
#define SPLIT3 64   // T-splits for gather pass -> 8*64    = 512 blocks
#define FBLK   8    // p-slices per batch in k_final -> 64 blocks, 16 outputs each

// Output layout: flattened tuple in reference order, all fp32
#define OFF_PROJ   0
#define OFF_SCORES 1024
#define OFF_IDX    1216
#define OFF_SEL    1240

// k_final dynamic smem: w-slice 64KB + normed 4KB + part 1KB + reduce pads
#define SMEM_FINAL (65536 + 4096 + 1024 + 128)

// Scratch (device globals; allocation-free)
__device__ float        g_score_partial[BB * LL * SPLIT1];
__device__ int          g_topk_idx[BB * TOPK];
__device__ float        g_topk_val[BB * TOPK];
__device__ unsigned int g_pooled_key[BB * DD];   // monotone-key atomic-max accum
__device__ int          g_cnt;                   // last-block counter (self-resetting)

// Monotone float <-> uint key: uint order == float order (exact max).
__device__ __forceinline__ unsigned int fkey(float v) {
    unsigned int u = __float_as_uint(v);
    return (u & 0x80000000u) ? ~u : (u | 0x80000000u);
}
__device__ __forceinline__ float finv(unsigned int k) {
    return __uint_as_float((k & 0x80000000u) ? (k ^ 0x80000000u) : ~k);
}

// ---------------------------------------------------------------------------
// Kernel 1: per-(b,l,s) score partials over 32 t-rows each; first 32 blocks
// also init g_pooled_key. The LAST block additionally does softmax + top-3.
// ---------------------------------------------------------------------------
__global__ __launch_bounds__(256) void k_scores(const float* __restrict__ x,
                                                const float* __restrict__ w_score,
                                                const float* __restrict__ b_score,
                                                float* __restrict__ out) {
    const int blk = blockIdx.x;           // 0 .. BB*LL*SPLIT1-1
    const int tid = threadIdx.x;

    // init atomic-max key accumulator (0 is the minimal key)
    if (blk < 32) g_pooled_key[blk * 256 + tid] = 0u;

    const int s   = blk % SPLIT1;
    const int bl  = blk / SPLIT1;
    const int l   = bl % LL;
    const int b   = bl / LL;

    const float4* __restrict__ base =
        (const float4*)(x + ((size_t)b * LP1 + (size_t)(l + 1)) * TT * DD);
    const float4 w4 = ((const float4*)w_score)[tid];

    float acc = 0.f;
    const int t0 = s * (TT / SPLIT1);     // 32 rows per block
    #pragma unroll 8
    for (int t = t0; t < t0 + TT / SPLIT1; ++t) {
        float4 v = base[(size_t)t * (DD / 4) + tid];
        acc += v.x * w4.x + v.y * w4.y + v.z * w4.z + v.w * w4.w;
    }

    __shared__ float sm[256];
    sm[tid] = acc;
    __syncthreads();
    #pragma unroll
    for (int st = 128; st > 0; st >>= 1) {
        if (tid < st) sm[tid] += sm[tid + st];
        __syncthreads();
    }

    // publish partial, then last-block detection
    __shared__ int s_last;
    if (tid == 0) {
        g_score_partial[bl * SPLIT1 + s] = sm[0];
        __threadfence();
        int old = atomicAdd(&g_cnt, 1);
        s_last = (old == BB * LL * SPLIT1 - 1);
    }
    __syncthreads();
    if (!s_last) return;

    // ---- fused top-k (runs in exactly one block, after all partials) ----
    __threadfence();
    __shared__ float sc[BB * LL];
    if (tid < BB * LL) {
        float v = 0.f;
        #pragma unroll
        for (int i = 0; i < SPLIT1; ++i) v += g_score_partial[tid * SPLIT1 + i];
        v = v * (1.0f / (float)TT) + b_score[0];
        sc[tid] = v;
        out[OFF_SCORES + tid] = v;
    }
    __syncthreads();

    if (tid < BB) {
        const int bb = tid;
        float m = -CUDART_INF_F;
        #pragma unroll
        for (int l2 = 0; l2 < LL; ++l2) m = fmaxf(m, sc[bb * LL + l2]);
        float p[LL];
        float sum = 0.f;
        #pragma unroll
        for (int l2 = 0; l2 < LL; ++l2) { p[l2] = expf(sc[bb * LL + l2] - m); sum += p[l2]; }
        const float inv = 1.0f / sum;
        #pragma unroll
        for (int l2 = 0; l2 < LL; ++l2) p[l2] *= inv;

        bool used[LL];
        #pragma unroll
        for (int l2 = 0; l2 < LL; ++l2) used[l2] = false;

        for (int k = 0; k < TOPK; ++k) {
            int   best = 0;
            float bv   = -CUDART_INF_F;
            #pragma unroll
            for (int l2 = 0; l2 < LL; ++l2) {
                if (!used[l2] && p[l2] > bv) { bv = p[l2]; best = l2; }
            }
            used[best] = true;
            g_topk_idx[bb * TOPK + k] = best;
            g_topk_val[bb * TOPK + k] = bv;
            out[OFF_IDX + bb * TOPK + k] = (float)best;
        }
    }
    // reset counter for the next graph replay (deterministic)
    if (tid == 0) g_cnt = 0;
}

// ---------------------------------------------------------------------------
// Kernel 3: gather 3 selected layers -> write selected_layers output
// (streaming stores), fused weighted sum + block-local max over T, then
// branchless key-atomic max into g_pooled_key. B descending (L2-hot first).
// ---------------------------------------------------------------------------
__global__ __launch_bounds__(256) void k_gather(const float* __restrict__ x,
                                                float* __restrict__ out) {
    const int blk = blockIdx.x;             // 0 .. BB*SPLIT3-1
    const int s   = blk % SPLIT3;
    const int b   = (BB - 1) - blk / SPLIT3;   // descending: hot batches first
    const int tid = threadIdx.x;

    const int i0 = g_topk_idx[b * TOPK + 0];
    const int i1 = g_topk_idx[b * TOPK + 1];
    const int i2 = g_topk_idx[b * TOPK + 2];
    const float v0 = g_topk_val[b * TOPK + 0];
    const float v1 = g_topk_val[b * TOPK + 1];
    const float v2 = g_topk_val[b * TOPK + 2];

    const float4* __restrict__ p0 =
        (const float4*)(x + ((size_t)b * LP1 + (size_t)(i0 + 1)) * TT * DD);
    const float4* __restrict__ p1 =
        (const float4*)(x + ((size_t)b * LP1 + (size_t)(i1 + 1)) * TT * DD);
    const float4* __restrict__ p2 =
        (const float4*)(x + ((size_t)b * LP1 + (size_t)(i2 + 1)) * TT * DD);

    float* __restrict__ sel = out + OFF_SEL;
    float4* __restrict__ o0 = (float4*)(sel + ((size_t)b * TOPK + 0) * TT * DD);
    float4* __restrict__ o1 = (float4*)(sel + ((size_t)b * TOPK + 1) * TT * DD);
    float4* __restrict__ o2 = (float4*)(sel + ((size_t)b * TOPK + 2) * TT * DD);

    const int TPS = TT / SPLIT3;   // 8 rows per block
    float4 mx = make_float4(-CUDART_INF_F, -CUDART_INF_F, -CUDART_INF_F, -CUDART_INF_F);

    #pragma unroll
    for (int tt = 0; tt < TPS; ++tt) {
        const size_t off = (size_t)(s * TPS + tt) * (DD / 4) + tid;
        float4 a = p0[off];
        float4 c = p1[off];
        float4 e = p2[off];
        __stcs(&o0[off], a);
        __stcs(&o1[off], c);
        __stcs(&o2[off], e);
        float4 w;
        w.x = v0 * a.x + v1 * c.x + v2 * e.x;
        w.y = v0 * a.y + v1 * c.y + v2 * e.y;
        w.z = v0 * a.z + v1 * c.z + v2 * e.z;
        w.w = v0 * a.w + v1 * c.w + v2 * e.w;
        mx.x = fmaxf(mx.x, w.x);
        mx.y = fmaxf(mx.y, w.y);
        mx.z = fmaxf(mx.z, w.z);
        mx.w = fmaxf(mx.w, w.w);
    }

    unsigned int* gp = g_pooled_key + (size_t)b * DD + tid * 4;
    atomicMax(gp + 0, fkey(mx.x));
    atomicMax(gp + 1, fkey(mx.y));
    atomicMax(gp + 2, fkey(mx.z));
    atomicMax(gp + 3, fkey(mx.w));
}

// ---------------------------------------------------------------------------
// Kernel 4 (v4, smem-staged): grid = BB*FBLK = 64, block = 256.
// Block (b, pb) computes outputs p in [16pb, 16pb+16).
// 1) each thread issues 16 independent LDG.128 covering the block's 64KB
//    w_proj slice (ONE DRAM round trip, fully parallel);
// 2) LN runs while those loads are in flight;
// 3) STS to smem, barrier, GEMV entirely from smem.
// ---------------------------------------------------------------------------
__global__ __launch_bounds__(256) void k_final(const float* __restrict__ gamma,
                                               const float* __restrict__ beta,
                                               const float* __restrict__ w_proj,
                                               const float* __restrict__ b_proj,
                                               float* __restrict__ out) {
    extern __shared__ float sbuf[];
    float* wsh    = sbuf;           // [1024][16] floats = 64KB
    float* normed = sbuf + 16384;   // [1024]
    float* part   = normed + DD;    // [256]
    float* red    = part + 256;     // [8]
    float* red2   = red + 8;        // [8]
    float* stats  = red2 + 8;       // [2]

    const int b    = blockIdx.x >> 3;     // FBLK = 8
    const int pb   = blockIdx.x & 7;
    const int tid  = threadIdx.x;
    const int lane = tid & 31, warp = tid >> 5;

    // --- 1) issue the w_proj slice loads (16 x LDG.128 per thread) ---
    float4 tmp[16];
    {
        const float* __restrict__ wbase = w_proj + pb * 16;
        #pragma unroll
        for (int j = 0; j < 16; ++j) {
            const int idx = tid + 256 * j;     // 0..4095
            const int row = idx >> 2;          // 0..1023 (d index)
            const int q   = idx & 3;           // 16B quarter within 64B row seg
            tmp[j] = *(const float4*)(wbase + (size_t)row * PP + q * 4);
        }
    }

    // --- 2) LN (overlaps the DRAM round trip above) ---
    {
        const uint4 k4 = ((const uint4*)(g_pooled_key + (size_t)b * DD))[tid];
        float4 v;
        v.x = finv(k4.x); v.y = finv(k4.y); v.z = finv(k4.z); v.w = finv(k4.w);

        float s1 = v.x + v.y + v.z + v.w;
        float s2 = v.x * v.x + v.y * v.y + v.z * v.z + v.w * v.w;
        #pragma unroll
        for (int o = 16; o > 0; o >>= 1) {
            s1 += __shfl_down_sync(0xffffffffu, s1, o);
            s2 += __shfl_down_sync(0xffffffffu, s2, o);
        }
        if (lane == 0) { red[warp] = s1; red2[warp] = s2; }
        __syncthreads();
        if (tid == 0) {
            float t1 = 0.f, t2 = 0.f;
            #pragma unroll
            for (int i = 0; i < 8; ++i) { t1 += red[i]; t2 += red2[i]; }
            float mu  = t1 * (1.0f / (float)DD);
            float var = t2 * (1.0f / (float)DD) - mu * mu;
            stats[0] = mu;
            stats[1] = rsqrtf(var + 1e-5f);
        }
        __syncthreads();
        const float mu = stats[0], rstd = stats[1];
        const float4 g4  = ((const float4*)gamma)[tid];
        const float4 be4 = ((const float4*)beta)[tid];
        float4 n;
        n.x = (v.x - mu) * rstd * g4.x + be4.x;
        n.y = (v.y - mu) * rstd * g4.y + be4.y;
        n.z = (v.z - mu) * rstd * g4.z + be4.z;
        n.w = (v.w - mu) * rstd * g4.w + be4.w;
        ((float4*)normed)[tid] = n;
    }

    // --- 3) stage w slice to smem ---
    #pragma unroll
    for (int j = 0; j < 16; ++j) {
        const int idx = tid + 256 * j;
        *(float4*)(wsh + (size_t)idx * 4) = tmp[j];   // wsh[row][q*4..q*4+3]
    }
    __syncthreads();

    // --- 4) GEMV from smem: thread (g = tid>>4, p = tid&15) sums rows
    //        r = g + 16k, k = 0..63. Conflict-free smem access. ---
    {
        const int p = tid & 15;
        const int g = tid >> 4;
        float a0 = 0.f, a1 = 0.f, a2 = 0.f, a3 = 0.f;
        #pragma unroll
        for (int k = 0; k < 64; k += 4) {
            const int r0 = g + 16 * (k + 0);
            const int r1 = g + 16 * (k + 1);
            const int r2 = g + 16 * (k + 2);
            const int r3 = g + 16 * (k + 3);
            a0 = fmaf(normed[r0], wsh[r0 * 16 + p], a0);
            a1 = fmaf(normed[r1], wsh[r1 * 16 + p], a1);
            a2 = fmaf(normed[r2], wsh[r2 * 16 + p], a2);
            a3 = fmaf(normed[r3], wsh[r3 * 16 + p], a3);
        }
        part[tid] = (a0 + a1) + (a2 + a3);
    }
    __syncthreads();
    if (tid < 16) {
        const int p = pb * 16 + tid;
        float acc = b_proj[p];
        #pragma unroll
        for (int g = 0; g < 16; ++g) acc += part[g * 16 + tid];
        out[OFF_PROJ + b * PP + p] = acc;
    }
}

// ---------------------------------------------------------------------------
// Launch
// ---------------------------------------------------------------------------
extern "C" void kernel_launch(void* const* d_in, const int* in_sizes, int n_in,
                              void* d_out, int out_size) {
    const float* x       = (const float*)d_in[0];  // wav2vec_ft (8,25,512,1024)
    const float* w_score = (const float*)d_in[1];  // (1024,1)
    const float* b_score = (const float*)d_in[2];  // (1,)
    const float* ln_g    = (const float*)d_in[3];  // (1024,)
    const float* ln_b    = (const float*)d_in[4];  // (1024,)
    const float* w_proj  = (const float*)d_in[5];  // (1024,128)
    const float* b_proj  = (const float*)d_in[6];  // (128,)
    float* out = (float*)d_out;

    static bool attr_set = false;
    if (!attr_set) {
        cudaFuncSetAttribute(k_final, cudaFuncAttributeMaxDynamicSharedMemorySize,
                             SMEM_FINAL);
        attr_set = true;
    }

    k_scores<<<BB * LL * SPLIT1, 256>>>(x, w_score, b_score, out);
    k_gather<<<BB * SPLIT3, 256>>>(x, out);
    k_final<<<BB * FBLK, 256, SMEM_FINAL>>>(ln_g, ln_b, w_proj, b_proj, out);
}

// round 13
// speedup vs baseline: 1.0466x; 1.0079x over previous
#include <cuda_runtime.h>
#include <math_constants.h>

// Problem constants (fixed shapes from setup_inputs)
#define BB 8
#define LP1 25
#define LL 24
#define TT 512
#define DD 1024
#define PP 128
#define TOPK 3

#define SPLIT1 16   // T-splits for score pass  -> 8*24*16 = 3072 blocks
#define SPLIT3 64   // T-splits for gather pass -> 8*64    = 512 blocks
#define FBLK   8    // p-slices per batch in k_final -> 64 blocks, 16 outputs each

// Output layout: flattened tuple in reference order, all fp32
#define OFF_PROJ   0
#define OFF_SCORES 1024
#define OFF_IDX    1216
#define OFF_SEL    1240

// k_final dynamic smem: w-slice 64KB + normed 4KB + part 1KB + reduce pads
#define SMEM_FINAL (65536 + 4096 + 1024 + 128)

// Scratch (device globals; allocation-free)
__device__ float g_score_partial[BB * LL * SPLIT1];
__device__ int   g_topk_idx[BB * TOPK];
__device__ float g_topk_val[BB * TOPK];
__device__ float g_max_partial[BB * SPLIT3 * DD];  // per-split max partials (2MB)
__device__ float g_pooled[BB * DD];                // reduced max (32KB)
__device__ int   g_cnt;                            // last-block counter

// ---------------------------------------------------------------------------
// Kernel 1: per-(b,l,s) score partials over 32 t-rows each.
// The LAST block additionally does softmax + top-3.
// ---------------------------------------------------------------------------
__global__ __launch_bounds__(256) void k_scores(const float* __restrict__ x,
                                                const float* __restrict__ w_score,
                                                const float* __restrict__ b_score,
                                                float* __restrict__ out) {
    const int blk = blockIdx.x;           // 0 .. BB*LL*SPLIT1-1
    const int tid = threadIdx.x;

    const int s   = blk % SPLIT1;
    const int bl  = blk / SPLIT1;
    const int l   = bl % LL;
    const int b   = bl / LL;

    const float4* __restrict__ base =
        (const float4*)(x + ((size_t)b * LP1 + (size_t)(l + 1)) * TT * DD);
    const float4 w4 = ((const float4*)w_score)[tid];

    float acc = 0.f;
    const int t0 = s * (TT / SPLIT1);     // 32 rows per block
    #pragma unroll 8
    for (int t = t0; t < t0 + TT / SPLIT1; ++t) {
        float4 v = base[(size_t)t * (DD / 4) + tid];
        acc += v.x * w4.x + v.y * w4.y + v.z * w4.z + v.w * w4.w;
    }

    __shared__ float sm[256];
    sm[tid] = acc;
    __syncthreads();
    #pragma unroll
    for (int st = 128; st > 0; st >>= 1) {
        if (tid < st) sm[tid] += sm[tid + st];
        __syncthreads();
    }

    // publish partial, then last-block detection
    __shared__ int s_last;
    if (tid == 0) {
        g_score_partial[bl * SPLIT1 + s] = sm[0];
        __threadfence();
        int old = atomicAdd(&g_cnt, 1);
        s_last = (old == BB * LL * SPLIT1 - 1);
    }
    __syncthreads();
    if (!s_last) return;

    // ---- fused top-k (runs in exactly one block, after all partials) ----
    __threadfence();
    __shared__ float sc[BB * LL];
    if (tid < BB * LL) {
        float v = 0.f;
        #pragma unroll
        for (int i = 0; i < SPLIT1; ++i) v += g_score_partial[tid * SPLIT1 + i];
        v = v * (1.0f / (float)TT) + b_score[0];
        sc[tid] = v;
        out[OFF_SCORES + tid] = v;
    }
    __syncthreads();

    if (tid < BB) {
        const int bb = tid;
        float m = -CUDART_INF_F;
        #pragma unroll
        for (int l2 = 0; l2 < LL; ++l2) m = fmaxf(m, sc[bb * LL + l2]);
        float p[LL];
        float sum = 0.f;
        #pragma unroll
        for (int l2 = 0; l2 < LL; ++l2) { p[l2] = expf(sc[bb * LL + l2] - m); sum += p[l2]; }
        const float inv = 1.0f / sum;
        #pragma unroll
        for (int l2 = 0; l2 < LL; ++l2) p[l2] *= inv;

        bool used[LL];
        #pragma unroll
        for (int l2 = 0; l2 < LL; ++l2) used[l2] = false;

        for (int k = 0; k < TOPK; ++k) {
            int   best = 0;
            float bv   = -CUDART_INF_F;
            #pragma unroll
            for (int l2 = 0; l2 < LL; ++l2) {
                if (!used[l2] && p[l2] > bv) { bv = p[l2]; best = l2; }
            }
            used[best] = true;
            g_topk_idx[bb * TOPK + k] = best;
            g_topk_val[bb * TOPK + k] = bv;
            out[OFF_IDX + bb * TOPK + k] = (float)best;
        }
    }
    // reset counter for the next graph replay (deterministic)
    if (tid == 0) g_cnt = 0;
}

// ---------------------------------------------------------------------------
// Kernel 3: gather 3 selected layers -> write selected_layers output
// (streaming stores), fused weighted sum + block-local max over T,
// DETERMINISTIC partial write (no atomics). B descending (L2-hot first).
// ---------------------------------------------------------------------------
__global__ __launch_bounds__(256) void k_gather(const float* __restrict__ x,
                                                float* __restrict__ out) {
    const int blk = blockIdx.x;             // 0 .. BB*SPLIT3-1
    const int s   = blk % SPLIT3;
    const int b   = (BB - 1) - blk / SPLIT3;   // descending: hot batches first
    const int tid = threadIdx.x;

    const int i0 = g_topk_idx[b * TOPK + 0];
    const int i1 = g_topk_idx[b * TOPK + 1];
    const int i2 = g_topk_idx[b * TOPK + 2];
    const float v0 = g_topk_val[b * TOPK + 0];
    const float v1 = g_topk_val[b * TOPK + 1];
    const float v2 = g_topk_val[b * TOPK + 2];

    const float4* __restrict__ p0 =
        (const float4*)(x + ((size_t)b * LP1 + (size_t)(i0 + 1)) * TT * DD);
    const float4* __restrict__ p1 =
        (const float4*)(x + ((size_t)b * LP1 + (size_t)(i1 + 1)) * TT * DD);
    const float4* __restrict__ p2 =
        (const float4*)(x + ((size_t)b * LP1 + (size_t)(i2 + 1)) * TT * DD);

    float* __restrict__ sel = out + OFF_SEL;
    float4* __restrict__ o0 = (float4*)(sel + ((size_t)b * TOPK + 0) * TT * DD);
    float4* __restrict__ o1 = (float4*)(sel + ((size_t)b * TOPK + 1) * TT * DD);
    float4* __restrict__ o2 = (float4*)(sel + ((size_t)b * TOPK + 2) * TT * DD);

    const int TPS = TT / SPLIT3;   // 8 rows per block
    float4 mx = make_float4(-CUDART_INF_F, -CUDART_INF_F, -CUDART_INF_F, -CUDART_INF_F);

    #pragma unroll
    for (int tt = 0; tt < TPS; ++tt) {
        const size_t off = (size_t)(s * TPS + tt) * (DD / 4) + tid;
        float4 a = p0[off];
        float4 c = p1[off];
        float4 e = p2[off];
        __stcs(&o0[off], a);
        __stcs(&o1[off], c);
        __stcs(&o2[off], e);
        float4 w;
        w.x = v0 * a.x + v1 * c.x + v2 * e.x;
        w.y = v0 * a.y + v1 * c.y + v2 * e.y;
        w.z = v0 * a.z + v1 * c.z + v2 * e.z;
        w.w = v0 * a.w + v1 * c.w + v2 * e.w;
        mx.x = fmaxf(mx.x, w.x);
        mx.y = fmaxf(mx.y, w.y);
        mx.z = fmaxf(mx.z, w.z);
        mx.w = fmaxf(mx.w, w.w);
    }

    // deterministic partial write — stays in L2, reduced by k_reduce
    ((float4*)(g_max_partial + ((size_t)b * SPLIT3 + s) * DD))[tid] = mx;
}

// ---------------------------------------------------------------------------
// Kernel 3.5: reduce 64 partials -> g_pooled. 32 blocks x 256 threads;
// thread owns one (b,d): 64 coalesced-stride loads, unrolled (high MLP).
// ---------------------------------------------------------------------------
__global__ __launch_bounds__(256) void k_reduce() {
    const int idx = blockIdx.x * 256 + threadIdx.x;   // 0..8191
    const int b   = idx >> 10;
    const int d   = idx & (DD - 1);
    const float* __restrict__ mp = g_max_partial + (size_t)b * SPLIT3 * DD + d;
    float m = -CUDART_INF_F;
    #pragma unroll 16
    for (int s = 0; s < SPLIT3; ++s)
        m = fmaxf(m, mp[(size_t)s * DD]);
    g_pooled[idx] = m;
}

// ---------------------------------------------------------------------------
// Kernel 4 (smem-staged): grid = BB*FBLK = 64, block = 256.
// Block (b, pb) computes outputs p in [16pb, 16pb+16).
// ---------------------------------------------------------------------------
__global__ __launch_bounds__(256) void k_final(const float* __restrict__ gamma,
                                               const float* __restrict__ beta,
                                               const float* __restrict__ w_proj,
                                               const float* __restrict__ b_proj,
                                               float* __restrict__ out) {
    extern __shared__ float sbuf[];
    float* wsh    = sbuf;           // [1024][16] floats = 64KB
    float* normed = sbuf + 16384;   // [1024]
    float* part   = normed + DD;    // [256]
    float* red    = part + 256;     // [8]
    float* red2   = red + 8;        // [8]
    float* stats  = red2 + 8;       // [2]

    const int b    = blockIdx.x >> 3;     // FBLK = 8
    const int pb   = blockIdx.x & 7;
    const int tid  = threadIdx.x;
    const int lane = tid & 31, warp = tid >> 5;

    // --- 1) issue the w_proj slice loads (16 x LDG.128 per thread) ---
    float4 tmp[16];
    {
        const float* __restrict__ wbase = w_proj + pb * 16;
        #pragma unroll
        for (int j = 0; j < 16; ++j) {
            const int idx = tid + 256 * j;     // 0..4095
            const int row = idx >> 2;          // 0..1023 (d index)
            const int q   = idx & 3;           // 16B quarter within 64B row seg
            tmp[j] = *(const float4*)(wbase + (size_t)row * PP + q * 4);
        }
    }

    // --- 2) LN (overlaps the DRAM round trip above) ---
    {
        const float4 v = ((const float4*)(g_pooled + (size_t)b * DD))[tid];

        float s1 = v.x + v.y + v.z + v.w;
        float s2 = v.x * v.x + v.y * v.y + v.z * v.z + v.w * v.w;
        #pragma unroll
        for (int o = 16; o > 0; o >>= 1) {
            s1 += __shfl_down_sync(0xffffffffu, s1, o);
            s2 += __shfl_down_sync(0xffffffffu, s2, o);
        }
        if (lane == 0) { red[warp] = s1; red2[warp] = s2; }
        __syncthreads();
        if (tid == 0) {
            float t1 = 0.f, t2 = 0.f;
            #pragma unroll
            for (int i = 0; i < 8; ++i) { t1 += red[i]; t2 += red2[i]; }
            float mu  = t1 * (1.0f / (float)DD);
            float var = t2 * (1.0f / (float)DD) - mu * mu;
            stats[0] = mu;
            stats[1] = rsqrtf(var + 1e-5f);
        }
        __syncthreads();
        const float mu = stats[0], rstd = stats[1];
        const float4 g4  = ((const float4*)gamma)[tid];
        const float4 be4 = ((const float4*)beta)[tid];
        float4 n;
        n.x = (v.x - mu) * rstd * g4.x + be4.x;
        n.y = (v.y - mu) * rstd * g4.y + be4.y;
        n.z = (v.z - mu) * rstd * g4.z + be4.z;
        n.w = (v.w - mu) * rstd * g4.w + be4.w;
        ((float4*)normed)[tid] = n;
    }

    // --- 3) stage w slice to smem ---
    #pragma unroll
    for (int j = 0; j < 16; ++j) {
        const int idx = tid + 256 * j;
        *(float4*)(wsh + (size_t)idx * 4) = tmp[j];   // wsh[row][q*4..q*4+3]
    }
    __syncthreads();

    // --- 4) GEMV from smem: thread (g = tid>>4, p = tid&15) ---
    {
        const int p = tid & 15;
        const int g = tid >> 4;
        float a0 = 0.f, a1 = 0.f, a2 = 0.f, a3 = 0.f;
        #pragma unroll
        for (int k = 0; k < 64; k += 4) {
            const int r0 = g + 16 * (k + 0);
            const int r1 = g + 16 * (k + 1);
            const int r2 = g + 16 * (k + 2);
            const int r3 = g + 16 * (k + 3);
            a0 = fmaf(normed[r0], wsh[r0 * 16 + p], a0);
            a1 = fmaf(normed[r1], wsh[r1 * 16 + p], a1);
            a2 = fmaf(normed[r2], wsh[r2 * 16 + p], a2);
            a3 = fmaf(normed[r3], wsh[r3 * 16 + p], a3);
        }
        part[tid] = (a0 + a1) + (a2 + a3);
    }
    __syncthreads();
    if (tid < 16) {
        const int p = pb * 16 + tid;
        float acc = b_proj[p];
        #pragma unroll
        for (int g = 0; g < 16; ++g) acc += part[g * 16 + tid];
        out[OFF_PROJ + b * PP + p] = acc;
    }
}

// ---------------------------------------------------------------------------
// Launch
// ---------------------------------------------------------------------------
extern "C" void kernel_launch(void* const* d_in, const int* in_sizes, int n_in,
                              void* d_out, int out_size) {
    const float* x       = (const float*)d_in[0];  // wav2vec_ft (8,25,512,1024)
    const float* w_score = (const float*)d_in[1];  // (1024,1)
    const float* b_score = (const float*)d_in[2];  // (1,)
    const float* ln_g    = (const float*)d_in[3];  // (1024,)
    const float* ln_b    = (const float*)d_in[4];  // (1024,)
    const float* w_proj  = (const float*)d_in[5];  // (1024,128)
    const float* b_proj  = (const float*)d_in[6];  // (128,)
    float* out = (float*)d_out;

    static bool attr_set = false;
    if (!attr_set) {
        cudaFuncSetAttribute(k_final, cudaFuncAttributeMaxDynamicSharedMemorySize,
                             SMEM_FINAL);
        attr_set = true;
    }

    k_scores<<<BB * LL * SPLIT1, 256>>>(x, w_score, b_score, out);
    k_gather<<<BB * SPLIT3, 256>>>(x, out);
    k_reduce<<<32, 256>>>();
    k_final<<<BB * FBLK, 256, SMEM_FINAL>>>(ln_g, ln_b, w_proj, b_proj, out);
}